// round 16
// baseline (speedup 1.0000x reference)
#include <cuda_runtime.h>
#include <cuda_fp16.h>
#include <cstdint>
#include <cstddef>

#define BB 2048
#define TT 64
#define II 128
#define HH 1024

// Static device scratch (no allocations allowed). h states fp16; c states fp32.
__device__ __half g_h1[2][(size_t)BB * HH];
__device__ float  g_c1[(size_t)BB * HH];
__device__ float  g_c2[(size_t)BB * HH];
__device__ __half g_hist[(size_t)(TT + 1) * BB * HH];  // h2 history, slot 0 = initial
__device__ __half g_xh[(size_t)BB * TT * II];          // fp16-rounded x
__device__ __align__(256) __half g_wp1[(size_t)32 * 18 * 128 * 72];  // packed layer1 W
__device__ __align__(256) __half g_wp2[(size_t)32 * 32 * 128 * 72];  // packed layer2 W
__device__ __align__(256) __half g_fcw[(size_t)II * HH];             // fp16 fc W

// Fast activations: EX2/RCP MUFU based, ~2ulp, correct saturation at +-inf.
__device__ __forceinline__ float sigf(float x) {
    return __fdividef(1.f, 1.f + __expf(-x));
}
__device__ __forceinline__ float tanhf_fast(float x) {
    return 1.f - __fdividef(2.f, __expf(2.f * x) + 1.f);
}

__device__ __forceinline__ void mma16(float* c, const uint32_t* a, uint32_t b0, uint32_t b1) {
    asm volatile(
        "mma.sync.aligned.m16n8k16.row.col.f32.f16.f16.f32 "
        "{%0,%1,%2,%3},{%4,%5,%6,%7},{%8,%9},{%0,%1,%2,%3};"
        : "+f"(c[0]), "+f"(c[1]), "+f"(c[2]), "+f"(c[3])
        : "r"(a[0]), "r"(a[1]), "r"(a[2]), "r"(a[3]), "r"(b0), "r"(b1));
}

#define LDSM4(r, addr) \
    asm volatile("ldmatrix.sync.aligned.m8n8.x4.shared.b16 {%0,%1,%2,%3}, [%4];" \
                 : "=r"((r)[0]), "=r"((r)[1]), "=r"((r)[2]), "=r"((r)[3]) : "r"(addr))

__device__ __forceinline__ uint32_t s2u(const void* p) {
    uint32_t a;
    asm("{ .reg .u64 t; cvta.to.shared.u64 t, %1; cvt.u32.u64 %0, t; }" : "=r"(a) : "l"(p));
    return a;
}
__device__ __forceinline__ void cpa16(uint32_t d, const void* s) {
    asm volatile("cp.async.cg.shared.global [%0], [%1], 16;" :: "r"(d), "l"(s));
}
#define CP_COMMIT() asm volatile("cp.async.commit_group;" ::: "memory")
#define CP_WAIT1()  asm volatile("cp.async.wait_group 1;" ::: "memory")

// ---------------------------------------------------------------------------
// Prep kernels
// ---------------------------------------------------------------------------
__global__ void prep_all(const float* __restrict__ x, const float* __restrict__ h1,
                         const float* __restrict__ h2, const float* __restrict__ fcw,
                         __half* __restrict__ xo, __half* __restrict__ h1o,
                         __half* __restrict__ h2o, __half* __restrict__ fcwo)
{
    const size_t NX = (size_t)BB * TT * II, SN = (size_t)BB * HH, NFC = (size_t)II * HH;
    const size_t total = NX + 2 * SN + NFC;
    size_t stride = (size_t)gridDim.x * blockDim.x;
    for (size_t i = (size_t)blockIdx.x * blockDim.x + threadIdx.x; i < total; i += stride) {
        if (i < NX)                xo[i] = __float2half_rn(x[i]);
        else if (i < NX + SN)      h1o[i - NX] = __float2half_rn(h1[i - NX]);
        else if (i < NX + 2 * SN)  h2o[i - NX - SN] = __float2half_rn(h2[i - NX - SN]);
        else                       fcwo[i - NX - 2 * SN] = __float2half_rn(fcw[i - NX - 2 * SN]);
    }
}
__global__ void h2f_kernel(const __half* __restrict__ in, float* __restrict__ out, size_t n) {
    size_t stride = (size_t)gridDim.x * blockDim.x;
    for (size_t i = (size_t)blockIdx.x * blockDim.x + threadIdx.x; i < n; i += stride)
        out[i] = __half2float(in[i]);
}

// Pack W into [tile_n=32][s64][l=128][72] fp16 smem-image (row stride 144B),
// gate-permuted: l -> gate l>>5, unit tile_n*32 + (l&31). j<64 data, rest pad.
__global__ void pack_w_kernel(const float* __restrict__ Wih, int ldwi, int Ki,
                              const float* __restrict__ Whh,
                              __half* __restrict__ out, int S) {
    size_t total = (size_t)32 * S * 128 * 72;
    size_t stride = (size_t)gridDim.x * blockDim.x;
    for (size_t idx = (size_t)blockIdx.x * blockDim.x + threadIdx.x; idx < total; idx += stride) {
        int j = (int)(idx % 72); size_t r = idx / 72;
        int l = (int)(r % 128); r /= 128;
        int s = (int)(r % S);   int tn = (int)(r / S);
        float v = 0.f;
        if (j < 64) {
            int k = s * 64 + j;
            int wr = (l >> 5) * HH + tn * 32 + (l & 31);
            v = (k < Ki) ? Wih[(size_t)wr * ldwi + k]
                         : Whh[(size_t)wr * HH + (k - Ki)];
        }
        out[idx] = __float2half_rn(v);
    }
}

// ---------------------------------------------------------------------------
// Gate GEMM + fused LSTM cell. Tile 128x128 (gate-permuted N), 256 threads.
// 8 warps 2(m)x4(n), each 64x32. fp16 m16n8k16, ldmatrix feed.
// K staged 64 wide, 3-deep cp.async pipeline, one barrier per stage.
// Prefetch for stage s+2 INTERLEAVED into the MMA block (2 cp.async per
// kc-chunk) so the LSU issue burst hides in HMMA issue slack instead of
// delaying barrier arrival. 2 CTAs/SM.
// ---------------------------------------------------------------------------
struct GP {
    const __half* A1; long lda1; int s1;   // s1 = #K64 stages from A1
    const __half* A2;                      // lda = HH
    int S;                                 // total K64 stages
    const __half* Wp;                      // packed weights base
    const float* b1; const float* b2;
    __half* H; float* C;
};

#define A_BYTES 18432              // 128 * 144
#define SM_BUF  36864              // A 128*144 + B 128*144
#define SM_TOTAL (1024 + 3 * SM_BUF)

__device__ __forceinline__ void gate_body(const GP& p, int bid, char* smem) {
    const uint32_t sb = s2u(smem);
    float* bias = (float*)smem;
    const int tid = threadIdx.x, lane = tid & 31, wid = tid >> 5;
    const int tile_m = bid >> 5, tile_n = bid & 31;
    const int bm = tile_m * 128;
    const int wm = wid >> 2, wn = wid & 3;        // 2x4 warp grid, warp 64x32
    const int mwarp = wm * 64, nwarp = wn * 32;

    if (tid < 128) {   // summed permuted bias (gates-major, 128 cols)
        int wr = (tid >> 5) * HH + tile_n * 32 + (tid & 31);
        bias[tid] = p.b1[wr] + p.b2[wr];
    }

    float acc[4][4][4];                // [mi(16m)][n8][4]
#pragma unroll
    for (int a = 0; a < 4; a++)
#pragma unroll
        for (int b = 0; b < 4; b++)
#pragma unroll
            for (int c = 0; c < 4; c++) acc[a][b][c] = 0.f;

    const __half* wp_base = p.Wp + (size_t)tile_n * p.S * (128 * 72);

    // ldmatrix per-thread offsets (bytes), 144B row stride
    const uint32_t arow = (uint32_t)((mwarp + (lane & 7) + ((lane >> 3) & 1) * 8) * 144
                                     + (lane >> 4) * 16);
    const uint32_t brow = (uint32_t)((nwarp + (lane & 7) + (lane >> 4) * 8) * 144
                                     + ((lane >> 3) & 1) * 16);

    auto load = [&](int s) {   // full 8-granule load (prologue only)
        const int buf = s % 3;
        const __half* A; long lda; int kk;
        if (s < p.s1) { A = p.A1; lda = p.lda1; kk = s * 64; }
        else          { A = p.A2; lda = HH;     kk = (s - p.s1) * 64; }
        const uint32_t ab = sb + 1024 + buf * SM_BUF;
        const __half* Arow = A + (size_t)bm * lda + kk;
#pragma unroll
        for (int i = 0; i < 4; i++) {
            int c = tid + i * 256, row = c >> 3, kc = c & 7;
            cpa16(ab + row * 144 + kc * 16, Arow + (size_t)row * lda + kc * 8);
        }
        const uint32_t bb2 = ab + A_BYTES;
        const __half* Ws = wp_base + (size_t)s * (128 * 72);
#pragma unroll
        for (int i = 0; i < 4; i++) {
            int c = tid + i * 256, row = c >> 3, kc = c & 7;
            cpa16(bb2 + row * 144 + kc * 16, Ws + row * 72 + kc * 8);
        }
    };

    load(0); CP_COMMIT();
    if (p.S > 1) load(1);
    CP_COMMIT();

    for (int s = 0; s < p.S; s++) {
        CP_WAIT1();            // group s complete (<=1 pending: s+1)
        __syncthreads();       // buf s visible + all warps done MMA(s-1)

        // Stage-(s+2) prefetch pointers (buffer (s+2)%3 = (s-1)%3, freed above)
        const int s2 = s + 2;
        const bool pf = s2 < p.S;
        const __half* Arow2 = nullptr; long lda2 = 0;
        const __half* Ws2 = nullptr;
        uint32_t ab2 = 0;
        if (pf) {
            ab2 = sb + 1024 + (s2 % 3) * SM_BUF;
            if (s2 < p.s1) { Arow2 = p.A1 + (size_t)bm * p.lda1 + s2 * 64; lda2 = p.lda1; }
            else           { Arow2 = p.A2 + (size_t)bm * HH + (s2 - p.s1) * 64; lda2 = HH; }
            Ws2 = wp_base + (size_t)s2 * (128 * 72);
        }

        const uint32_t abase = sb + 1024 + (s % 3) * SM_BUF;
        const uint32_t bbase = abase + A_BYTES;
#pragma unroll
        for (int kc = 0; kc < 4; kc++) {   // four k16 chunks per K64 stage
            uint32_t af[4][4], bf[2][4];
#pragma unroll
            for (int mi = 0; mi < 4; mi++)
                LDSM4(af[mi], abase + arow + mi * 2304 + kc * 32);
#pragma unroll
            for (int nb = 0; nb < 2; nb++)
                LDSM4(bf[nb], bbase + brow + nb * 2304 + kc * 32);
#pragma unroll
            for (int mi = 0; mi < 4; mi++)
#pragma unroll
                for (int nb = 0; nb < 2; nb++) {
                    mma16(acc[mi][2 * nb],     af[mi], bf[nb][0], bf[nb][1]);
                    mma16(acc[mi][2 * nb + 1], af[mi], bf[nb][2], bf[nb][3]);
                }
            // 2 of the 8 prefetch granules, hidden in HMMA issue slack
            if (pf) {
                if (kc < 2) {
#pragma unroll
                    for (int i = 0; i < 2; i++) {
                        int c = tid + (2 * kc + i) * 256, row = c >> 3, kcc = c & 7;
                        cpa16(ab2 + row * 144 + kcc * 16,
                              Arow2 + (size_t)row * lda2 + kcc * 8);
                    }
                } else {
#pragma unroll
                    for (int i = 0; i < 2; i++) {
                        int c = tid + (2 * (kc - 2) + i) * 256, row = c >> 3, kcc = c & 7;
                        cpa16(ab2 + A_BYTES + row * 144 + kcc * 16,
                              Ws2 + row * 72 + kcc * 8);
                    }
                }
            }
        }
        CP_COMMIT();
    }
    __syncthreads();   // all MMA done before epilogue reuses buffers

    // Epilogue: whole 128x128 tile staged through smem (128 x 132 floats)
    float* stage = (float*)(smem + 1024);
    const int gid = lane >> 2, tig = lane & 3;
#pragma unroll
    for (int mi = 0; mi < 4; mi++)
#pragma unroll
        for (int n8 = 0; n8 < 4; n8++) {
            int r0 = mwarp + mi * 16 + gid;
            int c = nwarp + n8 * 8 + 2 * tig;
            stage[r0 * 132 + c]           = acc[mi][n8][0];
            stage[r0 * 132 + c + 1]       = acc[mi][n8][1];
            stage[(r0 + 8) * 132 + c]     = acc[mi][n8][2];
            stage[(r0 + 8) * 132 + c + 1] = acc[mi][n8][3];
        }
    __syncthreads();
    {
        int r = tid >> 1, u0 = (tid & 1) * 16;
        int m = bm + r;
        float* crow = p.C + (size_t)m * HH + tile_n * 32;
        __half* hrow = p.H + (size_t)m * HH + tile_n * 32;
#pragma unroll
        for (int jb = 0; jb < 4; jb++) {
            float4 cv = *(float4*)(crow + u0 + jb * 4);
            float* cvp = (float*)&cv;
            __half hv[4];
#pragma unroll
            for (int e = 0; e < 4; e++) {
                int u = u0 + jb * 4 + e;
                float iv = sigf(stage[r * 132 + u] + bias[u]);
                float fv = sigf(stage[r * 132 + 32 + u] + bias[32 + u]);
                float gv = tanhf_fast(stage[r * 132 + 64 + u] + bias[64 + u]);
                float ov = sigf(stage[r * 132 + 96 + u] + bias[96 + u]);
                float cn = fv * cvp[e] + iv * gv;
                cvp[e] = cn;
                hv[e] = __float2half_rn(ov * tanhf_fast(cn));
            }
            *(float4*)(crow + u0 + jb * 4) = cv;
            *(uint2*)(hrow + u0 + jb * 4) = *(uint2*)hv;
        }
    }
}

__global__ __launch_bounds__(256, 2)
void step_gemm(GP pa, GP pb, int nb_a) {
    extern __shared__ __align__(16) char smem[];
    if ((int)blockIdx.x < nb_a) gate_body(pa, blockIdx.x, smem);
    else                        gate_body(pb, blockIdx.x - nb_a, smem);
}

// ---------------------------------------------------------------------------
// Batched fc over the whole h2 history (fp16, 256 threads, tile 128x128,
// 2 CTAs/SM). Mainloop order as R15 (MMA before prefetch).
// ---------------------------------------------------------------------------
#define SM_BUF_FC 20480            // A 128*80 + B 128*80
#define SM_TOTAL_FC (1024 + 3 * SM_BUF_FC)

__global__ __launch_bounds__(256, 2)
void fc_gemm(const __half* __restrict__ A, const __half* __restrict__ W,
             const float* __restrict__ bias_g, float* __restrict__ out)
{
    extern __shared__ __align__(16) char smem[];
    const uint32_t sb = s2u(smem);
    float* bias = (float*)smem;
    const int tid = threadIdx.x, lane = tid & 31, wid = tid >> 5;
    const int gid = lane >> 2, tig = lane & 3;
    const int bm = blockIdx.x * 128;
    const int mwarp = (wid >> 2) * 64, nwarp = (wid & 3) * 32;

    if (tid < II) bias[tid] = bias_g[tid];

    float acc[4][4][4];
#pragma unroll
    for (int a = 0; a < 4; a++)
#pragma unroll
        for (int b = 0; b < 4; b++)
#pragma unroll
            for (int c = 0; c < 4; c++) acc[a][b][c] = 0.f;

    const uint32_t arow = (uint32_t)((mwarp + (lane & 7) + ((lane >> 3) & 1) * 8) * 80
                                     + (lane >> 4) * 16);
    const uint32_t brow = (uint32_t)((nwarp + (lane & 7) + (lane >> 4) * 8) * 80
                                     + ((lane >> 3) & 1) * 16);

    auto load = [&](int s) {
        const int buf = s % 3;
        const uint32_t ab = sb + 1024 + buf * SM_BUF_FC;
        const uint32_t bb2 = ab + 10240;
        int kk = s * 32;
#pragma unroll
        for (int i = 0; i < 2; i++) {
            int c = tid + i * 256, row = c >> 2, kc = c & 3;
            cpa16(ab + row * 80 + kc * 16, A + (size_t)(bm + row) * HH + kk + kc * 8);
        }
#pragma unroll
        for (int i = 0; i < 2; i++) {
            int c = tid + i * 256, row = c >> 2, kc = c & 3;
            cpa16(bb2 + row * 80 + kc * 16, W + (size_t)row * HH + kk + kc * 8);
        }
    };

    load(0); CP_COMMIT();
    load(1); CP_COMMIT();

    for (int s = 0; s < 32; s++) {
        CP_WAIT1();
        __syncthreads();
        {
            const uint32_t abase = sb + 1024 + (s % 3) * SM_BUF_FC;
            const uint32_t bbase = abase + 10240;
#pragma unroll
            for (int kc = 0; kc < 2; kc++) {
                uint32_t af[4][4], bf[2][4];
#pragma unroll
                for (int mi = 0; mi < 4; mi++)
                    LDSM4(af[mi], abase + arow + mi * 1280 + kc * 32);
#pragma unroll
                for (int nb = 0; nb < 2; nb++)
                    LDSM4(bf[nb], bbase + brow + nb * 1280 + kc * 32);
#pragma unroll
                for (int mi = 0; mi < 4; mi++)
#pragma unroll
                    for (int nb = 0; nb < 2; nb++) {
                        mma16(acc[mi][2 * nb],     af[mi], bf[nb][0], bf[nb][1]);
                        mma16(acc[mi][2 * nb + 1], af[mi], bf[nb][2], bf[nb][3]);
                    }
            }
        }
        if (s + 2 < 32) load(s + 2);
        CP_COMMIT();
    }

#pragma unroll
    for (int mi = 0; mi < 4; mi++) {
        int r0 = bm + mwarp + mi * 16 + gid;
#pragma unroll
        for (int half = 0; half < 2; half++) {
            int m = r0 + half * 8;
            size_t orow = ((size_t)(m & (BB - 1)) * TT + (m >> 11)) * II;
#pragma unroll
            for (int n = 0; n < 4; n++) {
                int c = nwarp + n * 8 + 2 * tig;
                float2 v;
                v.x = acc[mi][n][half * 2 + 0] + bias[c];
                v.y = acc[mi][n][half * 2 + 1] + bias[c + 1];
                *(float2*)(out + orow + c) = v;
            }
        }
    }
}

// ---------------------------------------------------------------------------
extern "C" void kernel_launch(void* const* d_in, const int* in_sizes, int n_in,
                              void* d_out, int out_size)
{
    const float* x     = (const float*)d_in[0];
    const float* h1_in = (const float*)d_in[1];
    const float* c1_in = (const float*)d_in[2];
    const float* h2_in = (const float*)d_in[3];
    const float* c2_in = (const float*)d_in[4];
    const float* w_ih1 = (const float*)d_in[5];
    const float* w_hh1 = (const float*)d_in[6];
    const float* b_ih1 = (const float*)d_in[7];
    const float* b_hh1 = (const float*)d_in[8];
    const float* w_ih2 = (const float*)d_in[9];
    const float* w_hh2 = (const float*)d_in[10];
    const float* b_ih2 = (const float*)d_in[11];
    const float* b_hh2 = (const float*)d_in[12];
    const float* fc_w  = (const float*)d_in[13];
    const float* fc_b  = (const float*)d_in[14];
    float* out = (float*)d_out;

    __half *h1p, *histp, *xhp, *wp1, *wp2, *fcwp;
    float *c1p, *c2p;
    cudaGetSymbolAddress((void**)&h1p, g_h1);
    cudaGetSymbolAddress((void**)&c1p, g_c1);
    cudaGetSymbolAddress((void**)&c2p, g_c2);
    cudaGetSymbolAddress((void**)&histp, g_hist);
    cudaGetSymbolAddress((void**)&xhp, g_xh);
    cudaGetSymbolAddress((void**)&wp1, g_wp1);
    cudaGetSymbolAddress((void**)&wp2, g_wp2);
    cudaGetSymbolAddress((void**)&fcwp, g_fcw);

    const size_t SN = (size_t)BB * HH;
    const size_t SB = SN * sizeof(float);

    // Prep
    prep_all<<<2048, 256>>>(x, h1_in, h2_in, fc_w, xhp, h1p, histp, fcwp);
    cudaMemcpyAsync(c1p, c1_in, SB, cudaMemcpyDeviceToDevice);
    cudaMemcpyAsync(c2p, c2_in, SB, cudaMemcpyDeviceToDevice);
    pack_w_kernel<<<2048, 256>>>(w_ih1, II, II, w_hh1, wp1, 18);
    pack_w_kernel<<<2048, 256>>>(w_ih2, HH, HH, w_hh2, wp2, 32);

    cudaFuncSetAttribute(step_gemm, cudaFuncAttributeMaxDynamicSharedMemorySize, SM_TOTAL);
    cudaFuncSetAttribute(fc_gemm, cudaFuncAttributeMaxDynamicSharedMemorySize, SM_TOTAL_FC);

    auto mkL1 = [&](int t) {   // K = 128(x) + 1024(h) = 18 K64 stages
        GP p;
        p.A1 = xhp + (size_t)t * II; p.lda1 = TT * II; p.s1 = 2;
        p.A2 = h1p + (size_t)(t & 1) * SN;
        p.S = 18; p.Wp = wp1; p.b1 = b_ih1; p.b2 = b_hh1;
        p.H = h1p + (size_t)((t + 1) & 1) * SN; p.C = c1p;
        return p;
    };
    auto mkL2 = [&](int t) {   // K = 1024 + 1024 = 32 K64 stages
        GP p;
        p.A1 = h1p + (size_t)((t + 1) & 1) * SN; p.lda1 = HH; p.s1 = 16;
        p.A2 = histp + (size_t)t * SN;
        p.S = 32; p.Wp = wp2; p.b1 = b_ih2; p.b2 = b_hh2;
        p.H = histp + (size_t)(t + 1) * SN; p.C = c2p;
        return p;
    };

    {
        GP p = mkL1(0);
        step_gemm<<<512, 256, SM_TOTAL>>>(p, p, 512);
    }
    for (int t = 0; t < TT - 1; t++) {
        GP p2 = mkL2(t), p1 = mkL1(t + 1);
        step_gemm<<<1024, 256, SM_TOTAL>>>(p2, p1, 512);
    }
    {
        GP p = mkL2(TT - 1);
        step_gemm<<<512, 256, SM_TOTAL>>>(p, p, 512);
    }

    // Batched fc over all timesteps
    fc_gemm<<<1024, 256, SM_TOTAL_FC>>>(histp + SN, fcwp, fc_b, out);

    // Final states: output_seq ‖ h1 ‖ c1 ‖ h2 ‖ c2
    float* tail = out + (size_t)BB * TT * II;
    h2f_kernel<<<256, 256>>>(h1p, tail + 0 * SN, SN);   // H1[64] in buf 0
    cudaMemcpyAsync(tail + 1 * SN, c1p, SB, cudaMemcpyDeviceToDevice);
    h2f_kernel<<<256, 256>>>(histp + (size_t)TT * SN, tail + 2 * SN, SN);
    cudaMemcpyAsync(tail + 3 * SN, c2p, SB, cudaMemcpyDeviceToDevice);
}

// round 17
// speedup vs baseline: 1.0098x; 1.0098x over previous
#include <cuda_runtime.h>
#include <cuda_fp16.h>
#include <cstdint>
#include <cstddef>

#define BB 2048
#define TT 64
#define II 128
#define HH 1024

// Static device scratch (no allocations allowed). h states fp16; c states fp32.
__device__ __half g_h1[2][(size_t)BB * HH];
__device__ float  g_c1[(size_t)BB * HH];
__device__ float  g_c2[(size_t)BB * HH];
__device__ __half g_hist[(size_t)(TT + 1) * BB * HH];  // h2 history, slot 0 = initial
__device__ __half g_xh[(size_t)BB * TT * II];          // fp16-rounded x
__device__ __align__(256) __half g_wp1[(size_t)32 * 18 * 128 * 72];  // packed layer1 W
__device__ __align__(256) __half g_wp2[(size_t)32 * 32 * 128 * 72];  // packed layer2 W
__device__ __align__(256) __half g_fcw[(size_t)II * HH];             // fp16 fc W

// Fast activations: EX2/RCP MUFU based, ~2ulp, correct saturation at +-inf.
__device__ __forceinline__ float sigf(float x) {
    return __fdividef(1.f, 1.f + __expf(-x));
}
__device__ __forceinline__ float tanhf_fast(float x) {
    return 1.f - __fdividef(2.f, __expf(2.f * x) + 1.f);
}

__device__ __forceinline__ void mma16(float* c, const uint32_t* a, uint32_t b0, uint32_t b1) {
    asm volatile(
        "mma.sync.aligned.m16n8k16.row.col.f32.f16.f16.f32 "
        "{%0,%1,%2,%3},{%4,%5,%6,%7},{%8,%9},{%0,%1,%2,%3};"
        : "+f"(c[0]), "+f"(c[1]), "+f"(c[2]), "+f"(c[3])
        : "r"(a[0]), "r"(a[1]), "r"(a[2]), "r"(a[3]), "r"(b0), "r"(b1));
}

#define LDSM4(r, addr) \
    asm volatile("ldmatrix.sync.aligned.m8n8.x4.shared.b16 {%0,%1,%2,%3}, [%4];" \
                 : "=r"((r)[0]), "=r"((r)[1]), "=r"((r)[2]), "=r"((r)[3]) : "r"(addr))

__device__ __forceinline__ uint32_t s2u(const void* p) {
    uint32_t a;
    asm("{ .reg .u64 t; cvta.to.shared.u64 t, %1; cvt.u32.u64 %0, t; }" : "=r"(a) : "l"(p));
    return a;
}
__device__ __forceinline__ void cpa16(uint32_t d, const void* s) {
    asm volatile("cp.async.cg.shared.global [%0], [%1], 16;" :: "r"(d), "l"(s));
}
#define CP_COMMIT() asm volatile("cp.async.commit_group;" ::: "memory")
#define CP_WAIT1()  asm volatile("cp.async.wait_group 1;" ::: "memory")

// ---------------------------------------------------------------------------
// Prep kernels
// ---------------------------------------------------------------------------
__global__ void prep_all(const float* __restrict__ x, const float* __restrict__ h1,
                         const float* __restrict__ h2, const float* __restrict__ fcw,
                         __half* __restrict__ xo, __half* __restrict__ h1o,
                         __half* __restrict__ h2o, __half* __restrict__ fcwo)
{
    const size_t NX = (size_t)BB * TT * II, SN = (size_t)BB * HH, NFC = (size_t)II * HH;
    const size_t total = NX + 2 * SN + NFC;
    size_t stride = (size_t)gridDim.x * blockDim.x;
    for (size_t i = (size_t)blockIdx.x * blockDim.x + threadIdx.x; i < total; i += stride) {
        if (i < NX)                xo[i] = __float2half_rn(x[i]);
        else if (i < NX + SN)      h1o[i - NX] = __float2half_rn(h1[i - NX]);
        else if (i < NX + 2 * SN)  h2o[i - NX - SN] = __float2half_rn(h2[i - NX - SN]);
        else                       fcwo[i - NX - 2 * SN] = __float2half_rn(fcw[i - NX - 2 * SN]);
    }
}

// Fused finalization: tail = [h1_f32 | c1 | h2_f32 | c2], one sweep.
__global__ void finalize_kernel(const __half* __restrict__ h1f,
                                const float* __restrict__ c1,
                                const __half* __restrict__ h2f,
                                const float* __restrict__ c2,
                                float* __restrict__ tail)
{
    const size_t SN = (size_t)BB * HH;
    size_t stride = (size_t)gridDim.x * blockDim.x;
    for (size_t i = (size_t)blockIdx.x * blockDim.x + threadIdx.x; i < SN; i += stride) {
        tail[i]          = __half2float(h1f[i]);
        tail[SN + i]     = c1[i];
        tail[2 * SN + i] = __half2float(h2f[i]);
        tail[3 * SN + i] = c2[i];
    }
}

// Pack W into [tile_n=32][s64][l=128][72] fp16 smem-image (row stride 144B),
// gate-permuted: l -> gate l>>5, unit tile_n*32 + (l&31). j<64 data, rest pad.
__global__ void pack_w_kernel(const float* __restrict__ Wih, int ldwi, int Ki,
                              const float* __restrict__ Whh,
                              __half* __restrict__ out, int S) {
    size_t total = (size_t)32 * S * 128 * 72;
    size_t stride = (size_t)gridDim.x * blockDim.x;
    for (size_t idx = (size_t)blockIdx.x * blockDim.x + threadIdx.x; idx < total; idx += stride) {
        int j = (int)(idx % 72); size_t r = idx / 72;
        int l = (int)(r % 128); r /= 128;
        int s = (int)(r % S);   int tn = (int)(r / S);
        float v = 0.f;
        if (j < 64) {
            int k = s * 64 + j;
            int wr = (l >> 5) * HH + tn * 32 + (l & 31);
            v = (k < Ki) ? Wih[(size_t)wr * ldwi + k]
                         : Whh[(size_t)wr * HH + (k - Ki)];
        }
        out[idx] = __float2half_rn(v);
    }
}

// ---------------------------------------------------------------------------
// Gate GEMM + fused LSTM cell. Tile 128x128 (gate-permuted N), 256 threads.
// 8 warps 2(m)x4(n), each 64x32. fp16 m16n8k16, ldmatrix feed.
// K staged 64 wide, 3-deep cp.async pipeline, one barrier per stage.
// Mainloop order (R15): WAIT -> sync -> MMA(s) -> prefetch(s+2) -> COMMIT.
// 2 CTAs/SM (regs<=128, smem 111.6KB/CTA).
// ---------------------------------------------------------------------------
struct GP {
    const __half* A1; long lda1; int s1;   // s1 = #K64 stages from A1
    const __half* A2;                      // lda = HH
    int S;                                 // total K64 stages
    const __half* Wp;                      // packed weights base
    const float* b1; const float* b2;
    __half* H; float* C;
};

#define A_BYTES 18432              // 128 * 144
#define SM_BUF  36864              // A 128*144 + B 128*144
#define SM_TOTAL (1024 + 3 * SM_BUF)

__device__ __forceinline__ void gate_body(const GP& p, int bid, char* smem) {
    const uint32_t sb = s2u(smem);
    float* bias = (float*)smem;
    const int tid = threadIdx.x, lane = tid & 31, wid = tid >> 5;
    const int tile_m = bid >> 5, tile_n = bid & 31;
    const int bm = tile_m * 128;
    const int wm = wid >> 2, wn = wid & 3;        // 2x4 warp grid, warp 64x32
    const int mwarp = wm * 64, nwarp = wn * 32;

    if (tid < 128) {   // summed permuted bias (gates-major, 128 cols)
        int wr = (tid >> 5) * HH + tile_n * 32 + (tid & 31);
        bias[tid] = p.b1[wr] + p.b2[wr];
    }

    float acc[4][4][4];                // [mi(16m)][n8][4]
#pragma unroll
    for (int a = 0; a < 4; a++)
#pragma unroll
        for (int b = 0; b < 4; b++)
#pragma unroll
            for (int c = 0; c < 4; c++) acc[a][b][c] = 0.f;

    const __half* wp_base = p.Wp + (size_t)tile_n * p.S * (128 * 72);

    // ldmatrix per-thread offsets (bytes), 144B row stride
    const uint32_t arow = (uint32_t)((mwarp + (lane & 7) + ((lane >> 3) & 1) * 8) * 144
                                     + (lane >> 4) * 16);
    const uint32_t brow = (uint32_t)((nwarp + (lane & 7) + (lane >> 4) * 8) * 144
                                     + ((lane >> 3) & 1) * 16);

    auto load = [&](int s) {
        const int buf = s % 3;
        const __half* A; long lda; int kk;
        if (s < p.s1) { A = p.A1; lda = p.lda1; kk = s * 64; }
        else          { A = p.A2; lda = HH;     kk = (s - p.s1) * 64; }
        const uint32_t ab = sb + 1024 + buf * SM_BUF;
        const __half* Arow = A + (size_t)bm * lda + kk;
#pragma unroll
        for (int i = 0; i < 4; i++) {   // A: 128 rows x 8 granules = 1024
            int c = tid + i * 256, row = c >> 3, kc = c & 7;
            cpa16(ab + row * 144 + kc * 16, Arow + (size_t)row * lda + kc * 8);
        }
        const uint32_t bb2 = ab + A_BYTES;
        const __half* Ws = wp_base + (size_t)s * (128 * 72);
#pragma unroll
        for (int i = 0; i < 4; i++) {   // B: 128 rows x 8 granules = 1024
            int c = tid + i * 256, row = c >> 3, kc = c & 7;
            cpa16(bb2 + row * 144 + kc * 16, Ws + row * 72 + kc * 8);
        }
    };

    load(0); CP_COMMIT();
    if (p.S > 1) load(1);
    CP_COMMIT();

    for (int s = 0; s < p.S; s++) {
        CP_WAIT1();            // group s complete (<=1 pending: s+1)
        __syncthreads();       // buf s visible + all warps done MMA(s-1)
        {
            const uint32_t abase = sb + 1024 + (s % 3) * SM_BUF;
            const uint32_t bbase = abase + A_BYTES;
#pragma unroll
            for (int kc = 0; kc < 4; kc++) {   // four k16 chunks per K64 stage
                uint32_t af[4][4], bf[2][4];
#pragma unroll
                for (int mi = 0; mi < 4; mi++)
                    LDSM4(af[mi], abase + arow + mi * 2304 + kc * 32);
#pragma unroll
                for (int nb = 0; nb < 2; nb++)
                    LDSM4(bf[nb], bbase + brow + nb * 2304 + kc * 32);
#pragma unroll
                for (int mi = 0; mi < 4; mi++)
#pragma unroll
                    for (int nb = 0; nb < 2; nb++) {
                        mma16(acc[mi][2 * nb],     af[mi], bf[nb][0], bf[nb][1]);
                        mma16(acc[mi][2 * nb + 1], af[mi], bf[nb][2], bf[nb][3]);
                    }
            }
        }
        // Prefetch AFTER the MMA block (R15 ordering): LSU burst overlaps next
        // stage's slack. Buffer (s+2)%3 freed by the barrier above.
        if (s + 2 < p.S) load(s + 2);
        CP_COMMIT();
    }
    __syncthreads();   // all MMA done before epilogue reuses buffers

    // Epilogue: whole 128x128 tile staged through smem (128 x 132 floats)
    float* stage = (float*)(smem + 1024);
    const int gid = lane >> 2, tig = lane & 3;
#pragma unroll
    for (int mi = 0; mi < 4; mi++)
#pragma unroll
        for (int n8 = 0; n8 < 4; n8++) {
            int r0 = mwarp + mi * 16 + gid;
            int c = nwarp + n8 * 8 + 2 * tig;
            stage[r0 * 132 + c]           = acc[mi][n8][0];
            stage[r0 * 132 + c + 1]       = acc[mi][n8][1];
            stage[(r0 + 8) * 132 + c]     = acc[mi][n8][2];
            stage[(r0 + 8) * 132 + c + 1] = acc[mi][n8][3];
        }
    __syncthreads();
    {
        int r = tid >> 1, u0 = (tid & 1) * 16;
        int m = bm + r;
        float* crow = p.C + (size_t)m * HH + tile_n * 32;
        __half* hrow = p.H + (size_t)m * HH + tile_n * 32;
#pragma unroll
        for (int jb = 0; jb < 4; jb++) {
            float4 cv = *(float4*)(crow + u0 + jb * 4);
            float* cvp = (float*)&cv;
            __half hv[4];
#pragma unroll
            for (int e = 0; e < 4; e++) {
                int u = u0 + jb * 4 + e;
                float iv = sigf(stage[r * 132 + u] + bias[u]);
                float fv = sigf(stage[r * 132 + 32 + u] + bias[32 + u]);
                float gv = tanhf_fast(stage[r * 132 + 64 + u] + bias[64 + u]);
                float ov = sigf(stage[r * 132 + 96 + u] + bias[96 + u]);
                float cn = fv * cvp[e] + iv * gv;
                cvp[e] = cn;
                hv[e] = __float2half_rn(ov * tanhf_fast(cn));
            }
            *(float4*)(crow + u0 + jb * 4) = cv;
            *(uint2*)(hrow + u0 + jb * 4) = *(uint2*)hv;
        }
    }
}

__global__ __launch_bounds__(256, 2)
void step_gemm(GP pa, GP pb, int nb_a) {
    extern __shared__ __align__(16) char smem[];
    if ((int)blockIdx.x < nb_a) gate_body(pa, blockIdx.x, smem);
    else                        gate_body(pb, blockIdx.x - nb_a, smem);
}

// ---------------------------------------------------------------------------
// Batched fc over the whole h2 history (fp16, 256 threads, tile 128x128,
// 2 CTAs/SM). R15 mainloop ordering.
// ---------------------------------------------------------------------------
#define SM_BUF_FC 20480            // A 128*80 + B 128*80
#define SM_TOTAL_FC (1024 + 3 * SM_BUF_FC)

__global__ __launch_bounds__(256, 2)
void fc_gemm(const __half* __restrict__ A, const __half* __restrict__ W,
             const float* __restrict__ bias_g, float* __restrict__ out)
{
    extern __shared__ __align__(16) char smem[];
    const uint32_t sb = s2u(smem);
    float* bias = (float*)smem;
    const int tid = threadIdx.x, lane = tid & 31, wid = tid >> 5;
    const int gid = lane >> 2, tig = lane & 3;
    const int bm = blockIdx.x * 128;
    const int mwarp = (wid >> 2) * 64, nwarp = (wid & 3) * 32;

    if (tid < II) bias[tid] = bias_g[tid];

    float acc[4][4][4];
#pragma unroll
    for (int a = 0; a < 4; a++)
#pragma unroll
        for (int b = 0; b < 4; b++)
#pragma unroll
            for (int c = 0; c < 4; c++) acc[a][b][c] = 0.f;

    const uint32_t arow = (uint32_t)((mwarp + (lane & 7) + ((lane >> 3) & 1) * 8) * 80
                                     + (lane >> 4) * 16);
    const uint32_t brow = (uint32_t)((nwarp + (lane & 7) + (lane >> 4) * 8) * 80
                                     + ((lane >> 3) & 1) * 16);

    auto load = [&](int s) {
        const int buf = s % 3;
        const uint32_t ab = sb + 1024 + buf * SM_BUF_FC;
        const uint32_t bb2 = ab + 10240;
        int kk = s * 32;
#pragma unroll
        for (int i = 0; i < 2; i++) {
            int c = tid + i * 256, row = c >> 2, kc = c & 3;
            cpa16(ab + row * 80 + kc * 16, A + (size_t)(bm + row) * HH + kk + kc * 8);
        }
#pragma unroll
        for (int i = 0; i < 2; i++) {
            int c = tid + i * 256, row = c >> 2, kc = c & 3;
            cpa16(bb2 + row * 80 + kc * 16, W + (size_t)row * HH + kk + kc * 8);
        }
    };

    load(0); CP_COMMIT();
    load(1); CP_COMMIT();

    for (int s = 0; s < 32; s++) {
        CP_WAIT1();
        __syncthreads();
        {
            const uint32_t abase = sb + 1024 + (s % 3) * SM_BUF_FC;
            const uint32_t bbase = abase + 10240;
#pragma unroll
            for (int kc = 0; kc < 2; kc++) {
                uint32_t af[4][4], bf[2][4];
#pragma unroll
                for (int mi = 0; mi < 4; mi++)
                    LDSM4(af[mi], abase + arow + mi * 1280 + kc * 32);
#pragma unroll
                for (int nb = 0; nb < 2; nb++)
                    LDSM4(bf[nb], bbase + brow + nb * 1280 + kc * 32);
#pragma unroll
                for (int mi = 0; mi < 4; mi++)
#pragma unroll
                    for (int nb = 0; nb < 2; nb++) {
                        mma16(acc[mi][2 * nb],     af[mi], bf[nb][0], bf[nb][1]);
                        mma16(acc[mi][2 * nb + 1], af[mi], bf[nb][2], bf[nb][3]);
                    }
            }
        }
        if (s + 2 < 32) load(s + 2);
        CP_COMMIT();
    }

#pragma unroll
    for (int mi = 0; mi < 4; mi++) {
        int r0 = bm + mwarp + mi * 16 + gid;
#pragma unroll
        for (int half = 0; half < 2; half++) {
            int m = r0 + half * 8;
            size_t orow = ((size_t)(m & (BB - 1)) * TT + (m >> 11)) * II;
#pragma unroll
            for (int n = 0; n < 4; n++) {
                int c = nwarp + n * 8 + 2 * tig;
                float2 v;
                v.x = acc[mi][n][half * 2 + 0] + bias[c];
                v.y = acc[mi][n][half * 2 + 1] + bias[c + 1];
                *(float2*)(out + orow + c) = v;
            }
        }
    }
}

// ---------------------------------------------------------------------------
extern "C" void kernel_launch(void* const* d_in, const int* in_sizes, int n_in,
                              void* d_out, int out_size)
{
    const float* x     = (const float*)d_in[0];
    const float* h1_in = (const float*)d_in[1];
    const float* c1_in = (const float*)d_in[2];
    const float* h2_in = (const float*)d_in[3];
    const float* c2_in = (const float*)d_in[4];
    const float* w_ih1 = (const float*)d_in[5];
    const float* w_hh1 = (const float*)d_in[6];
    const float* b_ih1 = (const float*)d_in[7];
    const float* b_hh1 = (const float*)d_in[8];
    const float* w_ih2 = (const float*)d_in[9];
    const float* w_hh2 = (const float*)d_in[10];
    const float* b_ih2 = (const float*)d_in[11];
    const float* b_hh2 = (const float*)d_in[12];
    const float* fc_w  = (const float*)d_in[13];
    const float* fc_b  = (const float*)d_in[14];
    float* out = (float*)d_out;

    __half *h1p, *histp, *xhp, *wp1, *wp2, *fcwp;
    float *c1p, *c2p;
    cudaGetSymbolAddress((void**)&h1p, g_h1);
    cudaGetSymbolAddress((void**)&c1p, g_c1);
    cudaGetSymbolAddress((void**)&c2p, g_c2);
    cudaGetSymbolAddress((void**)&histp, g_hist);
    cudaGetSymbolAddress((void**)&xhp, g_xh);
    cudaGetSymbolAddress((void**)&wp1, g_wp1);
    cudaGetSymbolAddress((void**)&wp2, g_wp2);
    cudaGetSymbolAddress((void**)&fcwp, g_fcw);

    const size_t SN = (size_t)BB * HH;
    const size_t SB = SN * sizeof(float);

    // Prep
    prep_all<<<2048, 256>>>(x, h1_in, h2_in, fc_w, xhp, h1p, histp, fcwp);
    cudaMemcpyAsync(c1p, c1_in, SB, cudaMemcpyDeviceToDevice);
    cudaMemcpyAsync(c2p, c2_in, SB, cudaMemcpyDeviceToDevice);
    pack_w_kernel<<<2048, 256>>>(w_ih1, II, II, w_hh1, wp1, 18);
    pack_w_kernel<<<2048, 256>>>(w_ih2, HH, HH, w_hh2, wp2, 32);

    cudaFuncSetAttribute(step_gemm, cudaFuncAttributeMaxDynamicSharedMemorySize, SM_TOTAL);
    cudaFuncSetAttribute(fc_gemm, cudaFuncAttributeMaxDynamicSharedMemorySize, SM_TOTAL_FC);

    auto mkL1 = [&](int t) {   // K = 128(x) + 1024(h) = 18 K64 stages
        GP p;
        p.A1 = xhp + (size_t)t * II; p.lda1 = TT * II; p.s1 = 2;
        p.A2 = h1p + (size_t)(t & 1) * SN;
        p.S = 18; p.Wp = wp1; p.b1 = b_ih1; p.b2 = b_hh1;
        p.H = h1p + (size_t)((t + 1) & 1) * SN; p.C = c1p;
        return p;
    };
    auto mkL2 = [&](int t) {   // K = 1024 + 1024 = 32 K64 stages
        GP p;
        p.A1 = h1p + (size_t)((t + 1) & 1) * SN; p.lda1 = HH; p.s1 = 16;
        p.A2 = histp + (size_t)t * SN;
        p.S = 32; p.Wp = wp2; p.b1 = b_ih2; p.b2 = b_hh2;
        p.H = histp + (size_t)(t + 1) * SN; p.C = c2p;
        return p;
    };

    {
        GP p = mkL1(0);
        step_gemm<<<512, 256, SM_TOTAL>>>(p, p, 512);
    }
    for (int t = 0; t < TT - 1; t++) {
        GP p2 = mkL2(t), p1 = mkL1(t + 1);
        step_gemm<<<1024, 256, SM_TOTAL>>>(p2, p1, 512);
    }
    {
        GP p = mkL2(TT - 1);
        step_gemm<<<512, 256, SM_TOTAL>>>(p, p, 512);
    }

    // Batched fc over all timesteps
    fc_gemm<<<1024, 256, SM_TOTAL_FC>>>(histp + SN, fcwp, fc_b, out);

    // Fused finalization: output_seq ‖ h1 ‖ c1 ‖ h2 ‖ c2 in one sweep
    float* tail = out + (size_t)BB * TT * II;
    finalize_kernel<<<1024, 256>>>(h1p, c1p, histp + (size_t)TT * SN, c2p, tail);
}